// round 4
// baseline (speedup 1.0000x reference)
#include <cuda_runtime.h>

// NeuralVoxelField: trilinear interpolation of N points into a D*H*W*C fp32 grid.
// Layout: values[D][H][W][C], C=16 -> 64B per voxel, z-adjacent voxels contiguous.
//
// Strategy: 4 threads per point, each thread owns one float4 channel group.
// - corner gathers: 4 lanes of a point read one contiguous 64B segment per corner
// - z0/z1 corners are adjacent voxels -> paired 128B L2 lines
// - output: warp writes 8 points * 64B = 512B fully contiguous

constexpr int Dg = 128;
constexpr int Hg = 128;
constexpr int Wg = 128;
constexpr float INV_VOXEL = 20.0f;  // 1 / 0.05

__device__ __forceinline__ float4 lerp4(float4 a, float4 b, float t) {
    float4 r;
    r.x = fmaf(b.x - a.x, t, a.x);
    r.y = fmaf(b.y - a.y, t, a.y);
    r.z = fmaf(b.z - a.z, t, a.z);
    r.w = fmaf(b.w - a.w, t, a.w);
    return r;
}

__global__ __launch_bounds__(256, 8)
void trilerp_kernel(const float* __restrict__ points,
                    const float4* __restrict__ values,   // (D*H*W*16 floats) as float4
                    float4* __restrict__ out,            // (N*16 floats) as float4
                    int n)
{
    int t = blockIdx.x * blockDim.x + threadIdx.x;
    int p  = t >> 2;        // point index
    int cg = t & 3;         // channel group (4 floats each)
    if (p >= n) return;

    // All 4 lanes of a point read the same 12B -> broadcast in L1.
    float x = __ldg(&points[p * 3 + 0]) * INV_VOXEL;
    float y = __ldg(&points[p * 3 + 1]) * INV_VOXEL;
    float z = __ldg(&points[p * 3 + 2]) * INV_VOXEL;

    int x0 = min(max(__float2int_rd(x), 0), Dg - 1);
    int y0 = min(max(__float2int_rd(y), 0), Hg - 1);
    int z0 = min(max(__float2int_rd(z), 0), Wg - 1);
    int x1 = min(x0 + 1, Dg - 1);
    int y1 = min(y0 + 1, Hg - 1);
    int z1 = min(z0 + 1, Wg - 1);

    float xd = x - (float)x0;
    float yd = y - (float)y0;
    float zd = z - (float)z0;

    // voxel -> float4 index: lin*4 + cg   (16 floats = 4 float4 per voxel)
    int b00 = ((x0 * Hg + y0) * Wg) * 4 + cg;
    int b01 = ((x0 * Hg + y1) * Wg) * 4 + cg;
    int b10 = ((x1 * Hg + y0) * Wg) * 4 + cg;
    int b11 = ((x1 * Hg + y1) * Wg) * 4 + cg;
    int z0o = z0 * 4;
    int z1o = z1 * 4;

    // Issue all 8 gathers up front -> MLP=8 per thread.
    float4 c000 = values[b00 + z0o];
    float4 c001 = values[b00 + z1o];
    float4 c010 = values[b01 + z0o];
    float4 c011 = values[b01 + z1o];
    float4 c100 = values[b10 + z0o];
    float4 c101 = values[b10 + z1o];
    float4 c110 = values[b11 + z0o];
    float4 c111 = values[b11 + z1o];

    float4 c00 = lerp4(c000, c100, xd);
    float4 c01 = lerp4(c001, c101, xd);
    float4 c10 = lerp4(c010, c110, xd);
    float4 c11 = lerp4(c011, c111, xd);

    float4 c0 = lerp4(c00, c10, yd);
    float4 c1 = lerp4(c01, c11, yd);

    out[p * 4 + cg] = lerp4(c0, c1, zd);
}

extern "C" void kernel_launch(void* const* d_in, const int* in_sizes, int n_in,
                              void* d_out, int out_size) {
    const float*  points = (const float*)d_in[0];       // (N, 3) fp32
    const float4* values = (const float4*)d_in[1];      // (128,128,128,16) fp32
    float4* out = (float4*)d_out;                       // (N, 16) fp32

    int n = in_sizes[0] / 3;
    long long total = (long long)n * 4;
    int threads = 256;
    int blocks = (int)((total + threads - 1) / threads);
    trilerp_kernel<<<blocks, threads>>>(points, values, out, n);
}

// round 5
// speedup vs baseline: 1.0423x; 1.0423x over previous
#include <cuda_runtime.h>

// NeuralVoxelField: trilinear interpolation of N points into a 128^3 x 16 fp32 grid.
// 4 threads per point, one float4 channel-group each.
//
// R4 change: the grid (134MB) nearly fits L2 (126MB) and is the only reuse set.
// Output writes (128MB) and point reads (24MB) are touch-once streams -> issue
// them with evict-first (.cs) so they stop thrashing the grid out of L2.

constexpr int Dg = 128;
constexpr int Hg = 128;
constexpr int Wg = 128;
constexpr float INV_VOXEL = 20.0f;  // 1 / 0.05

__device__ __forceinline__ float4 lerp4(float4 a, float4 b, float t) {
    float4 r;
    r.x = fmaf(b.x - a.x, t, a.x);
    r.y = fmaf(b.y - a.y, t, a.y);
    r.z = fmaf(b.z - a.z, t, a.z);
    r.w = fmaf(b.w - a.w, t, a.w);
    return r;
}

__global__ __launch_bounds__(256, 8)
void trilerp_kernel(const float* __restrict__ points,
                    const float4* __restrict__ values,   // (D*H*W*16 floats) as float4
                    float4* __restrict__ out,            // (N*16 floats) as float4
                    int n)
{
    int t = blockIdx.x * blockDim.x + threadIdx.x;
    int p  = t >> 2;        // point index
    int cg = t & 3;         // channel group (4 floats each)
    if (p >= n) return;

    // Streaming (evict-first) loads: points are read once.
    float x = __ldcs(&points[p * 3 + 0]) * INV_VOXEL;
    float y = __ldcs(&points[p * 3 + 1]) * INV_VOXEL;
    float z = __ldcs(&points[p * 3 + 2]) * INV_VOXEL;

    int x0 = min(max(__float2int_rd(x), 0), Dg - 1);
    int y0 = min(max(__float2int_rd(y), 0), Hg - 1);
    int z0 = min(max(__float2int_rd(z), 0), Wg - 1);
    int x1 = min(x0 + 1, Dg - 1);
    int y1 = min(y0 + 1, Hg - 1);
    int z1 = min(z0 + 1, Wg - 1);

    float xd = x - (float)x0;
    float yd = y - (float)y0;
    float zd = z - (float)z0;

    // voxel -> float4 index: lin*4 + cg   (16 floats = 4 float4 per voxel)
    int b00 = ((x0 * Hg + y0) * Wg) * 4 + cg;
    int b01 = ((x0 * Hg + y1) * Wg) * 4 + cg;
    int b10 = ((x1 * Hg + y0) * Wg) * 4 + cg;
    int b11 = ((x1 * Hg + y1) * Wg) * 4 + cg;
    int z0o = z0 * 4;
    int z1o = z1 * 4;

    // Grid gathers on the default caching path (this is the L2 reuse set).
    float4 c000 = values[b00 + z0o];
    float4 c001 = values[b00 + z1o];
    float4 c010 = values[b01 + z0o];
    float4 c011 = values[b01 + z1o];
    float4 c100 = values[b10 + z0o];
    float4 c101 = values[b10 + z1o];
    float4 c110 = values[b11 + z0o];
    float4 c111 = values[b11 + z1o];

    float4 c00 = lerp4(c000, c100, xd);
    float4 c01 = lerp4(c001, c101, xd);
    float4 c10 = lerp4(c010, c110, xd);
    float4 c11 = lerp4(c011, c111, xd);

    float4 c0 = lerp4(c00, c10, yd);
    float4 c1 = lerp4(c01, c11, yd);

    // Streaming (evict-first) store: output is written once, never re-read.
    __stcs(&out[p * 4 + cg], lerp4(c0, c1, zd));
}

extern "C" void kernel_launch(void* const* d_in, const int* in_sizes, int n_in,
                              void* d_out, int out_size) {
    const float*  points = (const float*)d_in[0];       // (N, 3) fp32
    const float4* values = (const float4*)d_in[1];      // (128,128,128,16) fp32
    float4* out = (float4*)d_out;                       // (N, 16) fp32

    int n = in_sizes[0] / 3;
    long long total = (long long)n * 4;
    int threads = 256;
    int blocks = (int)((total + threads - 1) / threads);
    trilerp_kernel<<<blocks, threads>>>(points, values, out, n);
}